// round 1
// baseline (speedup 1.0000x reference)
#include <cuda_runtime.h>
#include <cstdint>

// Problem constants (fixed shapes per reference setup_inputs)
#define N_IMG 8
#define C_CH  256
#define H_IN  100
#define W_IN  100
#define OUT_H 7
#define OUT_W 7
#define SR    2
#define SPATIAL_SCALE 0.25f
#define NBINS (OUT_H*OUT_W)          // 49
#define NSAMP (OUT_H*SR)             // 14 (same for W since 7==7)
#define OUT_PER_ROI (C_CH*NBINS)     // 12544 floats
#define SMEM_OUT_BYTES (OUT_PER_ROI*4) // 50176

// NHWC scratch: 8*100*100*256 floats = 81.92 MB (static device array — legal scratch)
__device__ float g_nhwc[N_IMG * H_IN * W_IN * C_CH];

// ---------------------------------------------------------------------------
// Kernel 1: NCHW -> NHWC transpose. Treat each image as a 256 x 10000 matrix
// transpose (C x HW -> HW x C). Classic 32x32 tiled transpose, coalesced both ways.
// ---------------------------------------------------------------------------
__global__ void nchw_to_nhwc_kernel(const float* __restrict__ src) {
    __shared__ float tile[32][33];
    const int n      = blockIdx.z;
    const int cBase  = blockIdx.y * 32;
    const int hwBase = blockIdx.x * 32;
    const int tx = threadIdx.x;
    const int ty = threadIdx.y;

    const int HW = H_IN * W_IN;
    int hw = hwBase + tx;
    if (hw < HW) {
        const float* s = src + ((size_t)n * C_CH + (cBase + ty)) * HW + hw;
        #pragma unroll
        for (int i = 0; i < 32; i += 8)
            tile[ty + i][tx] = s[(size_t)i * HW];
    }
    __syncthreads();

    const int c = cBase + tx;
    #pragma unroll
    for (int i = 0; i < 32; i += 8) {
        int hw2 = hwBase + ty + i;
        if (hw2 < HW)
            g_nhwc[((size_t)n * HW + hw2) * C_CH + c] = tile[tx][ty + i];
    }
}

// ---------------------------------------------------------------------------
// Kernel 2: ROI align on NHWC data.
//   grid.x = K (one block per ROI), 256 threads.
//   tid & 63  -> channel quad index (64 quads * 4 ch = 256 channels, float4 loads)
//   tid >> 6  -> bin group (4 groups stride over the 49 bins)
// Within a warp: all lanes share the same bin/sample -> identical (y,x) ->
// 32 consecutive float4 loads = one contiguous 512B burst. Fully coalesced.
// Output staged in SMEM in final (C, 7, 7) per-ROI layout, written as float4.
// ---------------------------------------------------------------------------
__global__ __launch_bounds__(256) void roi_align_kernel(
    const float* __restrict__ rois,
    float* __restrict__ out,
    int K)
{
    __shared__ int   s_yoff0[NSAMP], s_yoff1[NSAMP];  // element offsets (b,row)*C
    __shared__ int   s_xoff0[NSAMP], s_xoff1[NSAMP];  // element offsets col*C
    __shared__ float s_ly[NSAMP], s_lx[NSAMP];
    __shared__ int   s_vy[NSAMP], s_vx[NSAMP];
    extern __shared__ float s_out[];                  // OUT_PER_ROI floats

    const int k   = blockIdx.x;
    const int tid = threadIdx.x;

    if (tid < NSAMP) {
        const float* r = rois + (size_t)k * 5;
        int   b  = (int)r[0];
        float x1 = r[1] * SPATIAL_SCALE;
        float y1 = r[2] * SPATIAL_SCALE;
        float x2 = r[3] * SPATIAL_SCALE;
        float y2 = r[4] * SPATIAL_SCALE;
        float roi_w = fmaxf(x2 - x1, 1.0f);
        float roi_h = fmaxf(y2 - y1, 1.0f);
        float bin_w = roi_w * (1.0f / OUT_W);
        float bin_h = roi_h * (1.0f / OUT_H);
        float t = ((float)tid + 0.5f) * (1.0f / SR);

        // y side
        float gy = y1 + bin_h * t;
        s_vy[tid] = (gy >= -1.0f && gy <= (float)H_IN) ? 1 : 0;
        float y  = fminf(fmaxf(gy, 0.0f), (float)(H_IN - 1));
        float yl = floorf(y);
        int y0   = (int)yl;
        int y1i  = min(y0 + 1, H_IN - 1);
        s_ly[tid]    = y - yl;
        s_yoff0[tid] = (b * H_IN * W_IN + y0  * W_IN) * C_CH;
        s_yoff1[tid] = (b * H_IN * W_IN + y1i * W_IN) * C_CH;

        // x side
        float gx = x1 + bin_w * t;
        s_vx[tid] = (gx >= -1.0f && gx <= (float)W_IN) ? 1 : 0;
        float x  = fminf(fmaxf(gx, 0.0f), (float)(W_IN - 1));
        float xl = floorf(x);
        int x0   = (int)xl;
        int x1i  = min(x0 + 1, W_IN - 1);
        s_lx[tid]    = x - xl;
        s_xoff0[tid] = x0  * C_CH;
        s_xoff1[tid] = x1i * C_CH;
    }
    __syncthreads();

    const int cg   = tid & 63;   // channel quad
    const int bg   = tid >> 6;   // bin group (0..3)
    const int coff = cg * 4;

    for (int bin = bg; bin < NBINS; bin += 4) {
        int ph = bin / OUT_W;
        int pw = bin - ph * OUT_W;
        float ax = 0.f, ay = 0.f, az = 0.f, aw = 0.f;
        #pragma unroll
        for (int s = 0; s < SR * SR; s++) {
            int iy = 2 * ph + (s >> 1);
            int ix = 2 * pw + (s & 1);
            if (s_vy[iy] & s_vx[ix]) {   // warp-uniform branch
                float ly = s_ly[iy], lx = s_lx[ix];
                int yo0 = s_yoff0[iy], yo1 = s_yoff1[iy];
                int xo0 = s_xoff0[ix], xo1 = s_xoff1[ix];
                const float4 v00 = *(const float4*)(g_nhwc + (yo0 + xo0 + coff));
                const float4 v01 = *(const float4*)(g_nhwc + (yo0 + xo1 + coff));
                const float4 v10 = *(const float4*)(g_nhwc + (yo1 + xo0 + coff));
                const float4 v11 = *(const float4*)(g_nhwc + (yo1 + xo1 + coff));
                float w00 = (1.f - ly) * (1.f - lx);
                float w01 = (1.f - ly) * lx;
                float w10 = ly * (1.f - lx);
                float w11 = ly * lx;
                ax += w00 * v00.x + w01 * v01.x + w10 * v10.x + w11 * v11.x;
                ay += w00 * v00.y + w01 * v01.y + w10 * v10.y + w11 * v11.y;
                az += w00 * v00.z + w01 * v01.z + w10 * v10.z + w11 * v11.z;
                aw += w00 * v00.w + w01 * v01.w + w10 * v10.w + w11 * v11.w;
            }
        }
        const float inv = 1.0f / (SR * SR);
        s_out[(coff + 0) * NBINS + bin] = ax * inv;
        s_out[(coff + 1) * NBINS + bin] = ay * inv;
        s_out[(coff + 2) * NBINS + bin] = az * inv;
        s_out[(coff + 3) * NBINS + bin] = aw * inv;
    }
    __syncthreads();

    // Coalesced float4 writeback of the whole per-ROI output block.
    float4* o4 = (float4*)(out + (size_t)k * OUT_PER_ROI);
    const float4* s4 = (const float4*)s_out;
    for (int i = tid; i < OUT_PER_ROI / 4; i += 256)
        o4[i] = s4[i];
}

extern "C" void kernel_launch(void* const* d_in, const int* in_sizes, int n_in,
                              void* d_out, int out_size) {
    const float* input = (const float*)d_in[0];  // (8,256,100,100) f32
    const float* rois  = (const float*)d_in[1];  // (K,5) f32
    float* out = (float*)d_out;                  // (K,256,7,7) f32
    int K = in_sizes[1] / 5;

    // Opt into >48KB dynamic shared memory for the ROI kernel (not a stream op,
    // graph-capture safe; called unconditionally, deterministic).
    cudaFuncSetAttribute(roi_align_kernel,
                         cudaFuncAttributeMaxDynamicSharedMemorySize,
                         SMEM_OUT_BYTES);

    dim3 tgrid((H_IN * W_IN + 31) / 32, C_CH / 32, N_IMG);
    dim3 tblock(32, 8);
    nchw_to_nhwc_kernel<<<tgrid, tblock>>>(input);

    roi_align_kernel<<<K, 256, SMEM_OUT_BYTES>>>(rois, out, K);
}

// round 2
// speedup vs baseline: 1.0643x; 1.0643x over previous
#include <cuda_runtime.h>
#include <cstdint>

// Problem constants (fixed shapes per reference setup_inputs)
#define N_IMG 8
#define C_CH  256
#define H_IN  100
#define W_IN  100
#define OUT_H 7
#define OUT_W 7
#define SR    2
#define SPATIAL_SCALE 0.25f
#define NBINS (OUT_H*OUT_W)          // 49
#define NSAMP (OUT_H*SR)             // 14
#define OUT_PER_ROI (C_CH*NBINS)     // 12544 floats
#define CH_CHUNK 128                 // channels per pass
#define N_PASS   (C_CH / CH_CHUNK)   // 2
#define CHUNK_FLOATS (CH_CHUNK * NBINS)  // 6272 floats = 25088 B

// NHWC scratch: 8*100*100*256 floats = 81.92 MB (static device array — legal scratch)
__device__ float g_nhwc[N_IMG * H_IN * W_IN * C_CH];

// ---------------------------------------------------------------------------
// Kernel 1: NCHW -> NHWC transpose (C x HW -> HW x C per image).
// 32x32 tiled, coalesced both directions. ~5.9 TB/s effective, near LTS cap.
// ---------------------------------------------------------------------------
__global__ void nchw_to_nhwc_kernel(const float* __restrict__ src) {
    __shared__ float tile[32][33];
    const int n      = blockIdx.z;
    const int cBase  = blockIdx.y * 32;
    const int hwBase = blockIdx.x * 32;
    const int tx = threadIdx.x;
    const int ty = threadIdx.y;

    const int HW = H_IN * W_IN;
    int hw = hwBase + tx;
    if (hw < HW) {
        const float* s = src + ((size_t)n * C_CH + (cBase + ty)) * HW + hw;
        #pragma unroll
        for (int i = 0; i < 32; i += 8)
            tile[ty + i][tx] = s[(size_t)i * HW];
    }
    __syncthreads();

    const int c = cBase + tx;
    #pragma unroll
    for (int i = 0; i < 32; i += 8) {
        int hw2 = hwBase + ty + i;
        if (hw2 < HW)
            g_nhwc[((size_t)n * HW + hw2) * C_CH + c] = tile[tx][ty + i];
    }
}

// ---------------------------------------------------------------------------
// Kernel 2: ROI align on NHWC data. One block (256 thr) per ROI.
//   lane (tid&31)  -> channel quad within a 128-channel chunk (float4)
//   warp (tid>>5)  -> bin group (8 groups stride over 49 bins)
// A whole warp shares one bin -> warp-uniform control, each corner load is
// one contiguous 512B burst. Validity folded into per-sample edge weights
// (branchless -> all 16 LDG.128 per bin batch for MLP). Output staged in a
// 25KB SMEM chunk (128 ch x 49 bins) per pass, written back as float4.
// ---------------------------------------------------------------------------
__global__ __launch_bounds__(256, 6) void roi_align_kernel(
    const float* __restrict__ rois,
    float* __restrict__ out,
    int K)
{
    __shared__ int   s_oy0[NSAMP], s_oy1[NSAMP];   // (b,row)*C element offsets
    __shared__ int   s_ox0[NSAMP], s_ox1[NSAMP];   // col*C element offsets
    __shared__ float s_wy0[NSAMP], s_wy1[NSAMP];   // validity-folded y weights
    __shared__ float s_wx0[NSAMP], s_wx1[NSAMP];   // validity-folded x weights
    __shared__ float s_out[CHUNK_FLOATS];          // 25088 B staging

    const int k   = blockIdx.x;
    const int tid = threadIdx.x;

    if (tid < NSAMP) {
        const float* r = rois + (size_t)k * 5;
        int   b  = (int)r[0];
        float x1 = r[1] * SPATIAL_SCALE;
        float y1 = r[2] * SPATIAL_SCALE;
        float x2 = r[3] * SPATIAL_SCALE;
        float y2 = r[4] * SPATIAL_SCALE;
        float roi_w = fmaxf(x2 - x1, 1.0f);
        float roi_h = fmaxf(y2 - y1, 1.0f);
        float bin_w = roi_w * (1.0f / OUT_W);
        float bin_h = roi_h * (1.0f / OUT_H);
        float t = ((float)tid + 0.5f) * (1.0f / SR);

        // y side
        float gy = y1 + bin_h * t;
        float vy = (gy >= -1.0f && gy <= (float)H_IN) ? 1.0f : 0.0f;
        float y  = fminf(fmaxf(gy, 0.0f), (float)(H_IN - 1));
        float yl = floorf(y);
        int y0   = (int)yl;
        int y1i  = min(y0 + 1, H_IN - 1);
        float ly = y - yl;
        s_wy0[tid] = vy * (1.0f - ly);
        s_wy1[tid] = vy * ly;
        s_oy0[tid] = (b * H_IN * W_IN + y0  * W_IN) * C_CH;
        s_oy1[tid] = (b * H_IN * W_IN + y1i * W_IN) * C_CH;

        // x side
        float gx = x1 + bin_w * t;
        float vx = (gx >= -1.0f && gx <= (float)W_IN) ? 1.0f : 0.0f;
        float x  = fminf(fmaxf(gx, 0.0f), (float)(W_IN - 1));
        float xl = floorf(x);
        int x0   = (int)xl;
        int x1i  = min(x0 + 1, W_IN - 1);
        float lx = x - xl;
        s_wx0[tid] = vx * (1.0f - lx);
        s_wx1[tid] = vx * lx;
        s_ox0[tid] = x0  * C_CH;
        s_ox1[tid] = x1i * C_CH;
    }
    __syncthreads();

    const int lane4 = (tid & 31) * 4;   // channel offset within chunk
    const int bg    = tid >> 5;         // bin group (0..7)

    #pragma unroll
    for (int p = 0; p < N_PASS; p++) {
        const int cbase = p * CH_CHUNK + lane4;

        for (int bin = bg; bin < NBINS; bin += 8) {
            int ph = bin / OUT_W;
            int pw = bin - ph * OUT_W;
            float ax = 0.f, ay = 0.f, az = 0.f, aw = 0.f;
            #pragma unroll
            for (int s = 0; s < SR * SR; s++) {
                int iy = 2 * ph + (s >> 1);
                int ix = 2 * pw + (s & 1);
                int yo0 = s_oy0[iy], yo1 = s_oy1[iy];
                int xo0 = s_ox0[ix], xo1 = s_ox1[ix];
                float wy0 = s_wy0[iy], wy1 = s_wy1[iy];
                float wx0 = s_wx0[ix], wx1 = s_wx1[ix];
                const float4 v00 = *(const float4*)(g_nhwc + (yo0 + xo0 + cbase));
                const float4 v01 = *(const float4*)(g_nhwc + (yo0 + xo1 + cbase));
                const float4 v10 = *(const float4*)(g_nhwc + (yo1 + xo0 + cbase));
                const float4 v11 = *(const float4*)(g_nhwc + (yo1 + xo1 + cbase));
                ax += wy0 * (wx0 * v00.x + wx1 * v01.x) + wy1 * (wx0 * v10.x + wx1 * v11.x);
                ay += wy0 * (wx0 * v00.y + wx1 * v01.y) + wy1 * (wx0 * v10.y + wx1 * v11.y);
                az += wy0 * (wx0 * v00.z + wx1 * v01.z) + wy1 * (wx0 * v10.z + wx1 * v11.z);
                aw += wy0 * (wx0 * v00.w + wx1 * v01.w) + wy1 * (wx0 * v10.w + wx1 * v11.w);
            }
            const float inv = 1.0f / (SR * SR);
            s_out[(lane4 + 0) * NBINS + bin] = ax * inv;
            s_out[(lane4 + 1) * NBINS + bin] = ay * inv;
            s_out[(lane4 + 2) * NBINS + bin] = az * inv;
            s_out[(lane4 + 3) * NBINS + bin] = aw * inv;
        }
        __syncthreads();

        // Coalesced float4 writeback of this channel chunk (contiguous in out).
        float4* o4 = (float4*)(out + (size_t)k * OUT_PER_ROI + p * CHUNK_FLOATS);
        const float4* s4 = (const float4*)s_out;
        #pragma unroll
        for (int i = tid; i < CHUNK_FLOATS / 4; i += 256)
            o4[i] = s4[i];
        __syncthreads();
    }
}

extern "C" void kernel_launch(void* const* d_in, const int* in_sizes, int n_in,
                              void* d_out, int out_size) {
    const float* input = (const float*)d_in[0];  // (8,256,100,100) f32
    const float* rois  = (const float*)d_in[1];  // (K,5) f32
    float* out = (float*)d_out;                  // (K,256,7,7) f32
    int K = in_sizes[1] / 5;

    dim3 tgrid((H_IN * W_IN + 31) / 32, C_CH / 32, N_IMG);
    dim3 tblock(32, 8);
    nchw_to_nhwc_kernel<<<tgrid, tblock>>>(input);

    roi_align_kernel<<<K, 256>>>(rois, out, K);
}